// round 11
// baseline (speedup 1.0000x reference)
#include <cuda_runtime.h>
#include <cuda_fp16.h>
#include <cstdint>

#define BB   4
#define NPQ  1024
#define NRK  1024
#define CDIM 1024
#define HH   16
#define DH   64

// Scratch (static device arrays: allocation-guard safe)
__device__ __half g_Qh[(size_t)BB * NPQ * CDIM];      // raw inputs, fp16
__device__ __half g_Kh[(size_t)BB * NRK * CDIM];
__device__ __half g_Wh[3 * (size_t)CDIM * CDIM];      // Wq, Wk, Wv fp16
__device__ __half g_q[(size_t)BB * NPQ * CDIM];       // projected q/k/v
__device__ __half g_k[(size_t)BB * NRK * CDIM];
__device__ __half g_v[(size_t)BB * NRK * CDIM];
__device__ __half g_P[(size_t)BB * HH * NPQ * NRK];   // 128 MB
__device__ float  g_rowsum[(size_t)BB * HH * NPQ];    // 256 KB

// ---------------------------------------------------------------------------
// helpers
// ---------------------------------------------------------------------------
__device__ __forceinline__ void mma_f16(float c[4], const uint32_t a[4],
                                        const uint32_t b[2]) {
    asm volatile(
        "mma.sync.aligned.m16n8k16.row.col.f32.f16.f16.f32 "
        "{%0,%1,%2,%3}, {%4,%5,%6,%7}, {%8,%9}, {%0,%1,%2,%3};"
        : "+f"(c[0]), "+f"(c[1]), "+f"(c[2]), "+f"(c[3])
        : "r"(a[0]), "r"(a[1]), "r"(a[2]), "r"(a[3]), "r"(b[0]), "r"(b[1]));
}

#define LDSM_X4(r, addr) \
    asm volatile("ldmatrix.sync.aligned.m8n8.x4.shared.b16 {%0,%1,%2,%3}, [%4];" \
        : "=r"((r)[0]), "=r"((r)[1]), "=r"((r)[2]), "=r"((r)[3]) : "r"(addr))
#define LDSM_X2(r, addr) \
    asm volatile("ldmatrix.sync.aligned.m8n8.x2.shared.b16 {%0,%1}, [%2];" \
        : "=r"((r)[0]), "=r"((r)[1]) : "r"(addr))
#define LDSM_X2_T(r, addr) \
    asm volatile("ldmatrix.sync.aligned.m8n8.x2.trans.shared.b16 {%0,%1}, [%2];" \
        : "=r"((r)[0]), "=r"((r)[1]) : "r"(addr))

__device__ __forceinline__ uint32_t smem_u32(const void* p) {
    uint32_t a;
    asm("{ .reg .u64 t; cvta.to.shared.u64 t, %1; cvt.u32.u64 %0, t; }"
        : "=r"(a) : "l"(p));
    return a;
}

#define CP_ASYNC16(dst, src) \
    asm volatile("cp.async.cg.shared.global [%0], [%1], 16;" \
                 :: "r"(dst), "l"(src) : "memory")
#define CP_COMMIT() asm volatile("cp.async.commit_group;" ::: "memory")
#define CP_WAIT1()  asm volatile("cp.async.wait_group 1;" ::: "memory")
#define CP_WAIT0()  asm volatile("cp.async.wait_group 0;" ::: "memory")

#define SCH 72   // scores q/k halves stride
#define PH  40   // A-tile halves stride (16+16 + 8 pad)
#define VSH 72   // V halves stride

// ---------------------------------------------------------------------------
// fp32 -> fp16 conversion (float4 units)
// ---------------------------------------------------------------------------
__global__ void __launch_bounds__(256) f2h_kernel(
    const float* __restrict__ in, __half* __restrict__ out, int n4)
{
    int i = blockIdx.x * 256 + threadIdx.x;
    if (i >= n4) return;
    float4 v = reinterpret_cast<const float4*>(in)[i];
    __half2* o = reinterpret_cast<__half2*>(out) + 2 * (size_t)i;
    o[0] = __floats2half2_rn(v.x, v.y);
    o[1] = __floats2half2_rn(v.z, v.w);
}

// ---------------------------------------------------------------------------
// Projection GEMM (NT, fp16 HMMA), batched over blockIdx.z in {0,1,2}:
//   z=0: q = Qh*Wq^T + bq ; z=1: k = Kh*Wk^T + bk ; z=2: v = Kh*Wv^T + bv
// Block 256x128, 8 warps (4m x 2n), warp 64x64, k-stage 16, 2-stage cp.async.
// ---------------------------------------------------------------------------
__global__ void __launch_bounds__(256, 1) proj_gemm(
    const __half* __restrict__ Qh, const __half* __restrict__ Kh,
    const __half* __restrict__ Wh,
    const float* __restrict__ bq, const float* __restrict__ bk,
    const float* __restrict__ bv,
    __half* __restrict__ qo, __half* __restrict__ ko, __half* __restrict__ vo)
{
    extern __shared__ __half sh[];
    __half* Ah = sh;                 // [256][40]
    __half* Bh = sh + 256 * PH;      // [128][40]

    const int zz = blockIdx.z;
    const __half* Ag = (zz == 0) ? Qh : Kh;
    const __half* Bg = Wh + (size_t)zz * CDIM * CDIM;
    const float* bias = (zz == 0) ? bq : ((zz == 1) ? bk : bv);
    __half* Cg = (zz == 0) ? qo : ((zz == 1) ? ko : vo);

    const int tid = threadIdx.x;
    const int m0 = blockIdx.y << 8, n0 = blockIdx.x << 7;
    const int warp = tid >> 5, lane = tid & 31;
    const int g = lane >> 2, t = lane & 3;
    const int wm = (warp >> 1) << 6;
    const int wn = (warp & 1) << 6;

    const uint32_t sA = smem_u32(Ah);
    const uint32_t sB = smem_u32(Bh);

    auto load_stage = [&](int kt) {
        const int so = (kt & 1) << 4;
        const int k0 = kt << 4;
        CP_ASYNC16(sA + ((tid * PH + so) << 1),
                   Ag + (size_t)(m0 + tid) * CDIM + k0);
        CP_ASYNC16(sA + ((tid * PH + so + 8) << 1),
                   Ag + (size_t)(m0 + tid) * CDIM + k0 + 8);
        {
            int r = tid >> 1, c = (tid & 1) << 3;
            CP_ASYNC16(sB + ((r * PH + so + c) << 1),
                       Bg + (size_t)(n0 + r) * CDIM + k0 + c);
        }
        CP_COMMIT();
    };

    float acc[4][8][4];
#pragma unroll
    for (int i = 0; i < 4; i++)
#pragma unroll
        for (int j = 0; j < 8; j++)
#pragma unroll
            for (int l = 0; l < 4; l++) acc[i][j][l] = 0.f;

    const int KT = CDIM / 16;
    load_stage(0);

    const int arow = lane & 15, acol = (lane >> 4) << 3;
    const int brow = lane & 7,  bcol = ((lane >> 3) & 1) << 3;

    for (int kt = 0; kt < KT; kt++) {
        const bool pf = (kt + 1 < KT);
        if (pf) { load_stage(kt + 1); CP_WAIT1(); } else { CP_WAIT0(); }
        __syncthreads();

        const int so = (kt & 1) << 4;
        uint32_t a[4][4], b[8][2];
#pragma unroll
        for (int mt = 0; mt < 4; mt++)
            LDSM_X4(a[mt], sA + (((wm + (mt << 4) + arow) * PH) + so + acol) * 2);
#pragma unroll
        for (int nt = 0; nt < 8; nt++)
            LDSM_X2(b[nt], sB + (((wn + (nt << 3) + brow) * PH) + so + bcol) * 2);
#pragma unroll
        for (int mt = 0; mt < 4; mt++)
#pragma unroll
            for (int nt = 0; nt < 8; nt++)
                mma_f16(acc[mt][nt], a[mt], b[nt]);
        __syncthreads();
    }

#pragma unroll
    for (int mt = 0; mt < 4; mt++) {
        int m = m0 + wm + (mt << 4) + g;
#pragma unroll
        for (int nt = 0; nt < 8; nt++) {
            int n = n0 + wn + (nt << 3) + 2 * t;
            float b0v = bias[n], b1v = bias[n + 1];
            *reinterpret_cast<__half2*>(Cg + (size_t)m * CDIM + n) =
                __floats2half2_rn(acc[mt][nt][0] + b0v, acc[mt][nt][1] + b1v);
            *reinterpret_cast<__half2*>(Cg + (size_t)(m + 8) * CDIM + n) =
                __floats2half2_rn(acc[mt][nt][2] + b0v, acc[mt][nt][3] + b1v);
        }
    }
}

// ---------------------------------------------------------------------------
// Scores: P = fp16(exp(q.k^T/32)), rowsum += rounded sums.  [R9/R10]
// ---------------------------------------------------------------------------
__global__ void __launch_bounds__(256, 2) scores_gemm(
    const __half* __restrict__ qg, const __half* __restrict__ kg,
    __half* __restrict__ P, float* __restrict__ rowsum)
{
    extern __shared__ __half sh[];
    __half* qs = sh;                // [128][72]
    __half* ks = sh + 128 * SCH;    // [128][72]

    const int tid = threadIdx.x;
    const int z = blockIdx.z;
    const long long zb = z >> 4, zh = z & 15;
    const __half* A = qg + zb * ((long long)NPQ * CDIM) + zh * DH;
    const __half* B = kg + zb * ((long long)NRK * CDIM) + zh * DH;
    __half* C = P + (long long)z * NPQ * NRK;
    const int m0 = blockIdx.y << 7, n0 = blockIdx.x << 7;

    const int warp = tid >> 5, lane = tid & 31;
    const int g = lane >> 2, t = lane & 3;
    const int wm = (warp >> 1) << 5;
    const int wn = (warp & 1) << 6;

    const uint32_t sq = smem_u32(qs);
    const uint32_t sk = smem_u32(ks);
    const int lrow = tid >> 1;
    const int lh = (tid & 1) << 5;

    {
        const __half* pa = A + (size_t)(m0 + lrow) * CDIM + lh;
        const __half* pb = B + (size_t)(n0 + lrow) * CDIM + lh;
        const uint32_t dq = sq + ((lrow * SCH + lh) << 1);
        const uint32_t dk = sk + ((lrow * SCH + lh) << 1);
#pragma unroll
        for (int i = 0; i < 4; i++) {
            CP_ASYNC16(dq + (i << 4), pa + (i << 3));
            CP_ASYNC16(dk + (i << 4), pb + (i << 3));
        }
        CP_COMMIT();
    }
    CP_WAIT0();
    __syncthreads();

    float acc[2][8][4];
#pragma unroll
    for (int i = 0; i < 2; i++)
#pragma unroll
        for (int j = 0; j < 8; j++)
#pragma unroll
            for (int l = 0; l < 4; l++) acc[i][j][l] = 0.f;

    const int arow = lane & 15, acol = (lane >> 4) << 3;
    const int brow = lane & 7,  bcol = ((lane >> 3) & 1) << 3;

#pragma unroll
    for (int kk = 0; kk < 64; kk += 16) {
        uint32_t a[2][4], b[8][2];
#pragma unroll
        for (int mt = 0; mt < 2; mt++)
            LDSM_X4(a[mt], sq + (((wm + (mt << 4) + arow) * SCH) + kk + acol) * 2);
#pragma unroll
        for (int nt = 0; nt < 8; nt++)
            LDSM_X2(b[nt], sk + (((wn + (nt << 3) + brow) * SCH) + kk + bcol) * 2);
#pragma unroll
        for (int mt = 0; mt < 2; mt++)
#pragma unroll
            for (int nt = 0; nt < 8; nt++)
                mma_f16(acc[mt][nt], a[mt], b[nt]);
    }

    const float alpha = 0.03125f;
#pragma unroll
    for (int mt = 0; mt < 2; mt++) {
        int m = m0 + wm + (mt << 4) + g;
        float r0 = 0.f, r1 = 0.f;
#pragma unroll
        for (int nt = 0; nt < 8; nt++) {
            int n = n0 + wn + (nt << 3) + 2 * t;
            __half h0 = __float2half_rn(__expf(acc[mt][nt][0] * alpha));
            __half h1 = __float2half_rn(__expf(acc[mt][nt][1] * alpha));
            __half h2 = __float2half_rn(__expf(acc[mt][nt][2] * alpha));
            __half h3 = __float2half_rn(__expf(acc[mt][nt][3] * alpha));
            r0 += __half2float(h0) + __half2float(h1);
            r1 += __half2float(h2) + __half2float(h3);
            *reinterpret_cast<__half2*>(C + (size_t)m * NRK + n) =
                __halves2half2(h0, h1);
            *reinterpret_cast<__half2*>(C + (size_t)(m + 8) * NRK + n) =
                __halves2half2(h2, h3);
        }
        r0 += __shfl_xor_sync(0xffffffffu, r0, 1);
        r0 += __shfl_xor_sync(0xffffffffu, r0, 2);
        r1 += __shfl_xor_sync(0xffffffffu, r1, 1);
        r1 += __shfl_xor_sync(0xffffffffu, r1, 2);
        if (t == 0) {
            float* rs = rowsum + (size_t)z * NPQ;
            atomicAdd(&rs[m], r0);
            atomicAdd(&rs[m + 8], r1);
        }
    }
}

// ---------------------------------------------------------------------------
// A_avg[b',q,r] = (1/16) sum_{b,j} P[b,4b'+j,q,r] * inv[b,4b'+j,q]
// Block = (bp, q-pair); 16B loads (8 halves/thread), 128 thr per row.
// bp reversed so the first wave hits the L2-resident tail of P.
// ---------------------------------------------------------------------------
__global__ void __launch_bounds__(256) avg_kernel(
    const __half* __restrict__ P, const float* __restrict__ rowsum,
    float* __restrict__ Aavg)
{
    __shared__ float sinv[2][16];
    const int bp = 3 - (blockIdx.x >> 9);
    const int qp = blockIdx.x & 511;
    const int t = threadIdx.x;
    const int row = t >> 7;        // 0/1
    const int ch = t & 127;        // 8-half chunk
    const int q = qp * 2 + row;

    if (t < 32) {
        int r2 = t >> 4, idx = t & 15;
        int b = idx >> 2, j = idx & 3;
        sinv[r2][idx] = 1.0f /
            rowsum[((size_t)(b * HH + bp * 4 + j)) * NPQ + qp * 2 + r2];
    }
    __syncthreads();

    float a0 = 0.f, a1 = 0.f, a2 = 0.f, a3 = 0.f;
    float a4 = 0.f, a5 = 0.f, a6 = 0.f, a7 = 0.f;
#pragma unroll
    for (int b = 0; b < 4; b++)
#pragma unroll
        for (int j = 0; j < 4; j++) {
            const __half* p = P +
                ((((size_t)(b * HH + bp * 4 + j)) << 10 | q) << 10) + ch * 8;
            uint4 u = *reinterpret_cast<const uint4*>(p);
            const __half2* h = reinterpret_cast<const __half2*>(&u);
            float f = sinv[row][b * 4 + j];
            float2 f0 = __half22float2(h[0]);
            float2 f1 = __half22float2(h[1]);
            float2 f2 = __half22float2(h[2]);
            float2 f3 = __half22float2(h[3]);
            a0 = fmaf(f0.x, f, a0); a1 = fmaf(f0.y, f, a1);
            a2 = fmaf(f1.x, f, a2); a3 = fmaf(f1.y, f, a3);
            a4 = fmaf(f2.x, f, a4); a5 = fmaf(f2.y, f, a5);
            a6 = fmaf(f3.x, f, a6); a7 = fmaf(f3.y, f, a7);
        }
    const float sc = 1.0f / 16.0f;
    float* dst = Aavg + (((size_t)(bp << 10 | q)) << 10) + ch * 8;
    *reinterpret_cast<float4*>(dst) =
        make_float4(a0 * sc, a1 * sc, a2 * sc, a3 * sc);
    *reinterpret_cast<float4*>(dst + 4) =
        make_float4(a4 * sc, a5 * sc, a6 * sc, a7 * sc);
}

// ---------------------------------------------------------------------------
// Out GEMM (NN): O = inv * (P @ V). Block 128x64, 8 warps (4m x 2n),
// warp 32x32, k-stage 16, 2-stage cp.async, 2 CTAs/SM.
// ---------------------------------------------------------------------------
__global__ void __launch_bounds__(256, 2) out_gemm(
    const __half* __restrict__ Pg, const __half* __restrict__ Vg,
    const float* __restrict__ rowsum, float* __restrict__ Og)
{
    extern __shared__ __half sh[];
    __half* Ah = sh;                  // [128][40]
    __half* Vs = sh + 128 * PH;       // [32][72]

    const int tid = threadIdx.x;
    const int z = blockIdx.y;
    const long long zb = z >> 4, zh = z & 15;
    const __half* A = Pg + ((long long)z * NPQ) * NRK;
    const __half* B = Vg + zb * ((long long)NRK * CDIM) + zh * DH;
    float* C = Og + zb * ((long long)NPQ * CDIM) + zh * DH;

    const int m0 = blockIdx.x << 7;
    const int warp = tid >> 5, lane = tid & 31;
    const int g = lane >> 2, t = lane & 3;
    const int wm = (warp >> 1) << 5;   // 0,32,64,96
    const int wn = (warp & 1) << 5;    // 0,32

    const uint32_t sA = smem_u32(Ah);
    const uint32_t sV = smem_u32(Vs);

    auto load_stage = [&](int kt) {
        const int so = (kt & 1) << 4;
        const int k0 = kt << 4;
        {
            int r = tid >> 1, c = (tid & 1) << 3;
            CP_ASYNC16(sA + ((r * PH + so + c) << 1),
                       A + (size_t)(m0 + r) * NRK + k0 + c);
        }
        if (tid < 128) {
            int row = tid >> 3, col = (tid & 7) << 3;
            CP_ASYNC16(sV + (((so + row) * VSH + col) << 1),
                       B + (size_t)(k0 + row) * CDIM + col);
        }
        CP_COMMIT();
    };

    float acc[2][4][4];
#pragma unroll
    for (int i = 0; i < 2; i++)
#pragma unroll
        for (int j = 0; j < 4; j++)
#pragma unroll
            for (int l = 0; l < 4; l++) acc[i][j][l] = 0.f;

    const int KT = NRK / 16;
    load_stage(0);

    const int arow = lane & 15, acol = (lane >> 4) << 3;
    const int bkrow = lane & 15;

    for (int kt = 0; kt < KT; kt++) {
        const bool pf = (kt + 1 < KT);
        if (pf) { load_stage(kt + 1); CP_WAIT1(); } else { CP_WAIT0(); }
        __syncthreads();

        const int so = (kt & 1) << 4;
        uint32_t a[2][4], b[4][2];
#pragma unroll
        for (int mt = 0; mt < 2; mt++)
            LDSM_X4(a[mt], sA + (((wm + (mt << 4) + arow) * PH) + so + acol) * 2);
#pragma unroll
        for (int nt = 0; nt < 4; nt++)
            LDSM_X2_T(b[nt], sV + (((so + bkrow) * VSH) + wn + (nt << 3)) * 2);
#pragma unroll
        for (int mt = 0; mt < 2; mt++)
#pragma unroll
            for (int nt = 0; nt < 4; nt++)
                mma_f16(acc[mt][nt], a[mt], b[nt]);
        __syncthreads();
    }

    const float* rs = rowsum + (size_t)z * NPQ;
#pragma unroll
    for (int mt = 0; mt < 2; mt++) {
        int m = m0 + wm + (mt << 4) + g;
        float i0 = 1.0f / rs[m];
        float i1 = 1.0f / rs[m + 8];
#pragma unroll
        for (int nt = 0; nt < 4; nt++) {
            int n = wn + (nt << 3) + 2 * t;
            float2 o0, o1;
            o0.x = acc[mt][nt][0] * i0; o0.y = acc[mt][nt][1] * i0;
            o1.x = acc[mt][nt][2] * i1; o1.y = acc[mt][nt][3] * i1;
            *reinterpret_cast<float2*>(C + (size_t)m * CDIM + n) = o0;
            *reinterpret_cast<float2*>(C + (size_t)(m + 8) * CDIM + n) = o1;
        }
    }
}

// ---------------------------------------------------------------------------
#define PROJ_SMEM ((256 * PH + 128 * PH) * 2)    // 30720 B
#define SC_SMEM   (2 * 128 * SCH * 2)            // 36864 B
#define OUT_SMEM  ((128 * PH + 32 * VSH) * 2)    // 14848 B

extern "C" void kernel_launch(void* const* d_in, const int* in_sizes, int n_in,
                              void* d_out, int out_size)
{
    const float* Q  = (const float*)d_in[0];
    const float* K  = (const float*)d_in[1];
    const float* Wq = (const float*)d_in[2];
    const float* bq = (const float*)d_in[3];
    const float* Wk = (const float*)d_in[4];
    const float* bk = (const float*)d_in[5];
    const float* Wv = (const float*)d_in[6];
    const float* bv = (const float*)d_in[7];

    float* O    = (float*)d_out;
    float* Aavg = O + (size_t)BB * NPQ * CDIM;

    static __half *pQh = nullptr, *pKh = nullptr, *pWh = nullptr;
    static __half *pq = nullptr, *pk = nullptr, *pv = nullptr, *pP = nullptr;
    static float* pR = nullptr;
    if (!pq) {
        cudaGetSymbolAddress((void**)&pQh, g_Qh);
        cudaGetSymbolAddress((void**)&pKh, g_Kh);
        cudaGetSymbolAddress((void**)&pWh, g_Wh);
        cudaGetSymbolAddress((void**)&pq, g_q);
        cudaGetSymbolAddress((void**)&pk, g_k);
        cudaGetSymbolAddress((void**)&pv, g_v);
        cudaGetSymbolAddress((void**)&pP, g_P);
        cudaGetSymbolAddress((void**)&pR, g_rowsum);
        cudaFuncSetAttribute(proj_gemm,
                             cudaFuncAttributeMaxDynamicSharedMemorySize, PROJ_SMEM);
        cudaFuncSetAttribute(scores_gemm,
                             cudaFuncAttributeMaxDynamicSharedMemorySize, SC_SMEM);
        cudaFuncSetAttribute(out_gemm,
                             cudaFuncAttributeMaxDynamicSharedMemorySize, OUT_SMEM);
    }

    cudaMemsetAsync(pR, 0, (size_t)BB * HH * NPQ * sizeof(float));

    // 0) fp32 -> fp16 conversions
    const int NX4 = (BB * NPQ * CDIM) / 4;
    const int NW4 = (CDIM * CDIM) / 4;
    f2h_kernel<<<(NX4 + 255) / 256, 256>>>(Q, pQh, NX4);
    f2h_kernel<<<(NX4 + 255) / 256, 256>>>(K, pKh, NX4);
    f2h_kernel<<<(NW4 + 255) / 256, 256>>>(Wq, pWh, NW4);
    f2h_kernel<<<(NW4 + 255) / 256, 256>>>(Wk, pWh + (size_t)CDIM * CDIM, NW4);
    f2h_kernel<<<(NW4 + 255) / 256, 256>>>(Wv, pWh + 2 * (size_t)CDIM * CDIM, NW4);

    // 1) projections, one batched launch (z = 0,1,2)
    dim3 gp(CDIM / 128, (BB * NPQ) / 256, 3);
    proj_gemm<<<gp, 256, PROJ_SMEM>>>(pQh, pKh, pWh, bq, bk, bv, pq, pk, pv);

    // 2) P = fp16(exp(q.k/32)), rowsum over rounded values
    dim3 gs(NRK / 128, NPQ / 128, BB * HH);
    scores_gemm<<<gs, 256, SC_SMEM>>>(pq, pk, pP, pR);

    // 3) A_avg = mean_{16}(P * inv)  (bp reversed for L2 tail reuse)
    avg_kernel<<<BB * (NPQ / 2), 256>>>(pP, pR, Aavg);

    // 4) O = (P @ V) * inv
    dim3 go(NPQ / 128, BB * HH);
    out_gemm<<<go, 256, OUT_SMEM>>>(pP, pv, pR, O);
}

// round 12
// speedup vs baseline: 1.0479x; 1.0479x over previous
#include <cuda_runtime.h>
#include <cuda_fp16.h>
#include <cstdint>

#define BB   4
#define NPQ  1024
#define NRK  1024
#define CDIM 1024
#define HH   16
#define DH   64

// Scratch (static device arrays: allocation-guard safe)
__device__ __half g_Qh[(size_t)BB * NPQ * CDIM];
__device__ __half g_Kh[(size_t)BB * NRK * CDIM];
__device__ __half g_Wh[3 * (size_t)CDIM * CDIM];
__device__ __half g_q[(size_t)BB * NPQ * CDIM];
__device__ __half g_k[(size_t)BB * NRK * CDIM];
__device__ __half g_v[(size_t)BB * NRK * CDIM];
__device__ __half g_P[(size_t)BB * HH * NPQ * NRK];   // 128 MB
__device__ float  g_rowsum[(size_t)BB * HH * NPQ];

// ---------------------------------------------------------------------------
__device__ __forceinline__ void mma_f16(float c[4], const uint32_t a[4],
                                        const uint32_t b[2]) {
    asm volatile(
        "mma.sync.aligned.m16n8k16.row.col.f32.f16.f16.f32 "
        "{%0,%1,%2,%3}, {%4,%5,%6,%7}, {%8,%9}, {%0,%1,%2,%3};"
        : "+f"(c[0]), "+f"(c[1]), "+f"(c[2]), "+f"(c[3])
        : "r"(a[0]), "r"(a[1]), "r"(a[2]), "r"(a[3]), "r"(b[0]), "r"(b[1]));
}

#define LDSM_X4(r, addr) \
    asm volatile("ldmatrix.sync.aligned.m8n8.x4.shared.b16 {%0,%1,%2,%3}, [%4];" \
        : "=r"((r)[0]), "=r"((r)[1]), "=r"((r)[2]), "=r"((r)[3]) : "r"(addr))
#define LDSM_X2(r, addr) \
    asm volatile("ldmatrix.sync.aligned.m8n8.x2.shared.b16 {%0,%1}, [%2];" \
        : "=r"((r)[0]), "=r"((r)[1]) : "r"(addr))
#define LDSM_X2_T(r, addr) \
    asm volatile("ldmatrix.sync.aligned.m8n8.x2.trans.shared.b16 {%0,%1}, [%2];" \
        : "=r"((r)[0]), "=r"((r)[1]) : "r"(addr))

__device__ __forceinline__ uint32_t smem_u32(const void* p) {
    uint32_t a;
    asm("{ .reg .u64 t; cvta.to.shared.u64 t, %1; cvt.u32.u64 %0, t; }"
        : "=r"(a) : "l"(p));
    return a;
}

#define CP_ASYNC16(dst, src) \
    asm volatile("cp.async.cg.shared.global [%0], [%1], 16;" \
                 :: "r"(dst), "l"(src) : "memory")
#define CP_COMMIT() asm volatile("cp.async.commit_group;" ::: "memory")
#define CP_WAIT1()  asm volatile("cp.async.wait_group 1;" ::: "memory")
#define CP_WAIT0()  asm volatile("cp.async.wait_group 0;" ::: "memory")

#define SCH 72    // q/k smem halves stride
#define VSH 72    // v smem halves stride
#define PSH 136   // P smem halves stride (128 + 8 pad)
#define PH  40    // proj A/B halves stride

// fused kernel smem layout (halves)
#define FQ_OFF 0
#define FK_OFF (128 * SCH)                  // 2 buffers
#define FV_OFF (FK_OFF + 2 * 128 * SCH)     // 2 buffers
#define FP_OFF (FV_OFF + 2 * 128 * VSH)
#define FR_OFF (FP_OFF + 128 * PSH)         // rowsum floats (as 256 halves)
#define F_SMEM ((FR_OFF + 256) * 2)         // 127488 B

// ---------------------------------------------------------------------------
__global__ void __launch_bounds__(256) f2h_kernel(
    const float* __restrict__ in, __half* __restrict__ out, int n4)
{
    int i = blockIdx.x * 256 + threadIdx.x;
    if (i >= n4) return;
    float4 v = reinterpret_cast<const float4*>(in)[i];
    __half2* o = reinterpret_cast<__half2*>(out) + 2 * (size_t)i;
    o[0] = __floats2half2_rn(v.x, v.y);
    o[1] = __floats2half2_rn(v.z, v.w);
}

// ---------------------------------------------------------------------------
// Projection GEMM (NT, fp16 HMMA), batched z in {0,1,2}. [R11]
// ---------------------------------------------------------------------------
__global__ void __launch_bounds__(256, 1) proj_gemm(
    const __half* __restrict__ Qh, const __half* __restrict__ Kh,
    const __half* __restrict__ Wh,
    const float* __restrict__ bq, const float* __restrict__ bk,
    const float* __restrict__ bv,
    __half* __restrict__ qo, __half* __restrict__ ko, __half* __restrict__ vo)
{
    extern __shared__ __half sh[];
    __half* Ah = sh;
    __half* Bh = sh + 256 * PH;

    const int zz = blockIdx.z;
    const __half* Ag = (zz == 0) ? Qh : Kh;
    const __half* Bg = Wh + (size_t)zz * CDIM * CDIM;
    const float* bias = (zz == 0) ? bq : ((zz == 1) ? bk : bv);
    __half* Cg = (zz == 0) ? qo : ((zz == 1) ? ko : vo);

    const int tid = threadIdx.x;
    const int m0 = blockIdx.y << 8, n0 = blockIdx.x << 7;
    const int warp = tid >> 5, lane = tid & 31;
    const int g = lane >> 2, t = lane & 3;
    const int wm = (warp >> 1) << 6;
    const int wn = (warp & 1) << 6;

    const uint32_t sA = smem_u32(Ah);
    const uint32_t sB = smem_u32(Bh);

    auto load_stage = [&](int kt) {
        const int so = (kt & 1) << 4;
        const int k0 = kt << 4;
        CP_ASYNC16(sA + ((tid * PH + so) << 1),
                   Ag + (size_t)(m0 + tid) * CDIM + k0);
        CP_ASYNC16(sA + ((tid * PH + so + 8) << 1),
                   Ag + (size_t)(m0 + tid) * CDIM + k0 + 8);
        {
            int r = tid >> 1, c = (tid & 1) << 3;
            CP_ASYNC16(sB + ((r * PH + so + c) << 1),
                       Bg + (size_t)(n0 + r) * CDIM + k0 + c);
        }
        CP_COMMIT();
    };

    float acc[4][8][4];
#pragma unroll
    for (int i = 0; i < 4; i++)
#pragma unroll
        for (int j = 0; j < 8; j++)
#pragma unroll
            for (int l = 0; l < 4; l++) acc[i][j][l] = 0.f;

    const int KT = CDIM / 16;
    load_stage(0);

    const int arow = lane & 15, acol = (lane >> 4) << 3;
    const int brow = lane & 7,  bcol = ((lane >> 3) & 1) << 3;

    for (int kt = 0; kt < KT; kt++) {
        const bool pf = (kt + 1 < KT);
        if (pf) { load_stage(kt + 1); CP_WAIT1(); } else { CP_WAIT0(); }
        __syncthreads();

        const int so = (kt & 1) << 4;
        uint32_t a[4][4], b[8][2];
#pragma unroll
        for (int mt = 0; mt < 4; mt++)
            LDSM_X4(a[mt], sA + (((wm + (mt << 4) + arow) * PH) + so + acol) * 2);
#pragma unroll
        for (int nt = 0; nt < 8; nt++)
            LDSM_X2(b[nt], sB + (((wn + (nt << 3) + brow) * PH) + so + bcol) * 2);
#pragma unroll
        for (int mt = 0; mt < 4; mt++)
#pragma unroll
            for (int nt = 0; nt < 8; nt++)
                mma_f16(acc[mt][nt], a[mt], b[nt]);
        __syncthreads();
    }

#pragma unroll
    for (int mt = 0; mt < 4; mt++) {
        int m = m0 + wm + (mt << 4) + g;
#pragma unroll
        for (int nt = 0; nt < 8; nt++) {
            int n = n0 + wn + (nt << 3) + 2 * t;
            float b0v = bias[n], b1v = bias[n + 1];
            *reinterpret_cast<__half2*>(Cg + (size_t)m * CDIM + n) =
                __floats2half2_rn(acc[mt][nt][0] + b0v, acc[mt][nt][1] + b1v);
            *reinterpret_cast<__half2*>(Cg + (size_t)(m + 8) * CDIM + n) =
                __floats2half2_rn(acc[mt][nt][2] + b0v, acc[mt][nt][3] + b1v);
        }
    }
}

// ---------------------------------------------------------------------------
// Fused scores + PV per (z, q-tile): loops all 8 r-chunks.
//   S = q.k^T (K=64) -> P = fp16(exp(S/32)) -> gmem + smem
//   O += P @ V (K=128/chunk); rowsum in-block; epilogue scales by 1/rowsum.
// 256 thr, 8 warps. S: warp 32x64 (wm, wnS). PV: warp 32x32 (wm, wnO).
// ---------------------------------------------------------------------------
__global__ void __launch_bounds__(256, 1) fused_spv(
    const __half* __restrict__ qg, const __half* __restrict__ kg,
    const __half* __restrict__ vg,
    __half* __restrict__ Pg, float* __restrict__ rowsum,
    float* __restrict__ Og)
{
    extern __shared__ __half sh[];
    __half* qs = sh + FQ_OFF;
    __half* ps = sh + FP_OFF;
    float* rows_s = reinterpret_cast<float*>(sh + FR_OFF);

    const int tid = threadIdx.x;
    const int z = blockIdx.y;
    const long long zb = z >> 4, zh = z & 15;
    const __half* Aq = qg + zb * ((long long)NPQ * CDIM) + zh * DH;
    const __half* Ak = kg + zb * ((long long)NRK * CDIM) + zh * DH;
    const __half* Av = vg + zb * ((long long)NRK * CDIM) + zh * DH;
    __half* Pz = Pg + (long long)z * NPQ * NRK;
    float* Oz = Og + zb * ((long long)NPQ * CDIM) + zh * DH;

    const int m0 = blockIdx.x << 7;
    const int warp = tid >> 5, lane = tid & 31;
    const int g = lane >> 2, t = lane & 3;
    const int wm  = (warp >> 1) << 5;   // 0,32,64,96
    const int wnS = (warp & 1) << 6;    // 0,64
    const int wnO = (warp & 1) << 5;    // 0,32

    const uint32_t sq = smem_u32(qs);
    const uint32_t sk = smem_u32(sh + FK_OFF);
    const uint32_t sv = smem_u32(sh + FV_OFF);
    const uint32_t sp = smem_u32(ps);

    const int lrow = tid >> 1;
    const int lh = (tid & 1) << 5;

    // chunk loader: k,v chunk rc into buffer rc&1
    auto load_kv = [&](int rc) {
        const int s = rc & 1;
        const int rbase = rc << 7;
        const __half* pk = Ak + (size_t)(rbase + lrow) * CDIM + lh;
        const __half* pv = Av + (size_t)(rbase + lrow) * CDIM + lh;
        const uint32_t dk = sk + ((s * 128 * SCH + lrow * SCH + lh) << 1);
        const uint32_t dv = sv + ((s * 128 * VSH + lrow * VSH + lh) << 1);
#pragma unroll
        for (int i = 0; i < 4; i++) {
            CP_ASYNC16(dk + (i << 4), pk + (i << 3));
            CP_ASYNC16(dv + (i << 4), pv + (i << 3));
        }
        CP_COMMIT();
    };

    // q tile load (once) + chunk 0, one group
    {
        const __half* pa = Aq + (size_t)(m0 + lrow) * CDIM + lh;
        const uint32_t dq = sq + ((lrow * SCH + lh) << 1);
#pragma unroll
        for (int i = 0; i < 4; i++)
            CP_ASYNC16(dq + (i << 4), pa + (i << 3));
    }
    load_kv(0);

    if (tid < 128) rows_s[tid] = 0.f;

    float oacc[2][4][4];
#pragma unroll
    for (int i = 0; i < 2; i++)
#pragma unroll
        for (int j = 0; j < 4; j++)
#pragma unroll
            for (int l = 0; l < 4; l++) oacc[i][j][l] = 0.f;

    float rsum[2][2] = {{0.f, 0.f}, {0.f, 0.f}};

    const int arow = lane & 15, acol = (lane >> 4) << 3;
    const int brow = lane & 7,  bcol = ((lane >> 3) & 1) << 3;
    const int bkrow = lane & 15;
    const float alpha = 0.03125f;

    for (int rc = 0; rc < 8; rc++) {
        const int s = rc & 1;
        if (rc + 1 < 8) { load_kv(rc + 1); CP_WAIT1(); } else { CP_WAIT0(); }
        __syncthreads();

        // ---- S = q.k^T (128x128, K=64) ----
        float sacc[2][8][4];
#pragma unroll
        for (int i = 0; i < 2; i++)
#pragma unroll
            for (int j = 0; j < 8; j++)
#pragma unroll
                for (int l = 0; l < 4; l++) sacc[i][j][l] = 0.f;

#pragma unroll
        for (int kk = 0; kk < 64; kk += 16) {
            uint32_t a[2][4], b[8][2];
#pragma unroll
            for (int mt = 0; mt < 2; mt++)
                LDSM_X4(a[mt],
                        sq + (((wm + (mt << 4) + arow) * SCH) + kk + acol) * 2);
#pragma unroll
            for (int nt = 0; nt < 8; nt++)
                LDSM_X2(b[nt],
                        sk + ((s * 128 * SCH +
                               (wnS + (nt << 3) + brow) * SCH) + kk + bcol) * 2);
#pragma unroll
            for (int mt = 0; mt < 2; mt++)
#pragma unroll
                for (int nt = 0; nt < 8; nt++)
                    mma_f16(sacc[mt][nt], a[mt], b[nt]);
        }

        // ---- exp -> P (gmem + smem), rowsum regs ----
        const int rbase = rc << 7;
#pragma unroll
        for (int mt = 0; mt < 2; mt++) {
            int mloc = wm + (mt << 4) + g;
#pragma unroll
            for (int nt = 0; nt < 8; nt++) {
                int n = wnS + (nt << 3) + 2 * t;
                __half h0 = __float2half_rn(__expf(sacc[mt][nt][0] * alpha));
                __half h1 = __float2half_rn(__expf(sacc[mt][nt][1] * alpha));
                __half h2 = __float2half_rn(__expf(sacc[mt][nt][2] * alpha));
                __half h3 = __float2half_rn(__expf(sacc[mt][nt][3] * alpha));
                rsum[mt][0] += __half2float(h0) + __half2float(h1);
                rsum[mt][1] += __half2float(h2) + __half2float(h3);
                __half2 p01 = __halves2half2(h0, h1);
                __half2 p23 = __halves2half2(h2, h3);
                *reinterpret_cast<__half2*>(
                    Pz + (size_t)(m0 + mloc) * NRK + rbase + n) = p01;
                *reinterpret_cast<__half2*>(
                    Pz + (size_t)(m0 + mloc + 8) * NRK + rbase + n) = p23;
                *reinterpret_cast<__half2*>(ps + mloc * PSH + n) = p01;
                *reinterpret_cast<__half2*>(ps + (mloc + 8) * PSH + n) = p23;
            }
        }
        __syncthreads();   // P smem visible to all warps

        // ---- O += P @ V (128x64, K=128) ----
#pragma unroll
        for (int kk = 0; kk < 128; kk += 16) {
            uint32_t a[2][4], b[4][2];
#pragma unroll
            for (int mt = 0; mt < 2; mt++)
                LDSM_X4(a[mt],
                        sp + (((wm + (mt << 4) + arow) * PSH) + kk + acol) * 2);
#pragma unroll
            for (int nt = 0; nt < 4; nt++)
                LDSM_X2_T(b[nt],
                          sv + ((s * 128 * VSH + (kk + bkrow) * VSH) +
                                wnO + (nt << 3)) * 2);
#pragma unroll
            for (int mt = 0; mt < 2; mt++)
#pragma unroll
                for (int nt = 0; nt < 4; nt++)
                    mma_f16(oacc[mt][nt], a[mt], b[nt]);
        }
        __syncthreads();   // P smem free for next chunk
    }

    // ---- rowsum reduce + store; inv in smem ----
#pragma unroll
    for (int mt = 0; mt < 2; mt++) {
        float r0 = rsum[mt][0], r1 = rsum[mt][1];
        r0 += __shfl_xor_sync(0xffffffffu, r0, 1);
        r0 += __shfl_xor_sync(0xffffffffu, r0, 2);
        r1 += __shfl_xor_sync(0xffffffffu, r1, 1);
        r1 += __shfl_xor_sync(0xffffffffu, r1, 2);
        if (t == 0) {
            atomicAdd(&rows_s[wm + (mt << 4) + g], r0);
            atomicAdd(&rows_s[wm + (mt << 4) + g + 8], r1);
        }
    }
    __syncthreads();
    if (tid < 128) {
        float sv_ = rows_s[tid];
        rowsum[(size_t)z * NPQ + m0 + tid] = sv_;
        rows_s[tid] = 1.0f / sv_;
    }
    __syncthreads();

    // ---- O epilogue ----
#pragma unroll
    for (int mt = 0; mt < 2; mt++) {
        int mloc = wm + (mt << 4) + g;
        float i0 = rows_s[mloc];
        float i1 = rows_s[mloc + 8];
#pragma unroll
        for (int nt = 0; nt < 4; nt++) {
            int n = wnO + (nt << 3) + 2 * t;
            float2 o0, o1;
            o0.x = oacc[mt][nt][0] * i0; o0.y = oacc[mt][nt][1] * i0;
            o1.x = oacc[mt][nt][2] * i1; o1.y = oacc[mt][nt][3] * i1;
            *reinterpret_cast<float2*>(Oz + (size_t)(m0 + mloc) * CDIM + n) = o0;
            *reinterpret_cast<float2*>(Oz + (size_t)(m0 + mloc + 8) * CDIM + n) = o1;
        }
    }
}

// ---------------------------------------------------------------------------
// A_avg  [R11: 16B loads, bp reversed]
// ---------------------------------------------------------------------------
__global__ void __launch_bounds__(256) avg_kernel(
    const __half* __restrict__ P, const float* __restrict__ rowsum,
    float* __restrict__ Aavg)
{
    __shared__ float sinv[2][16];
    const int bp = 3 - (blockIdx.x >> 9);
    const int qp = blockIdx.x & 511;
    const int t = threadIdx.x;
    const int row = t >> 7;
    const int ch = t & 127;
    const int q = qp * 2 + row;

    if (t < 32) {
        int r2 = t >> 4, idx = t & 15;
        int b = idx >> 2, j = idx & 3;
        sinv[r2][idx] = 1.0f /
            rowsum[((size_t)(b * HH + bp * 4 + j)) * NPQ + qp * 2 + r2];
    }
    __syncthreads();

    float a0 = 0.f, a1 = 0.f, a2 = 0.f, a3 = 0.f;
    float a4 = 0.f, a5 = 0.f, a6 = 0.f, a7 = 0.f;
#pragma unroll
    for (int b = 0; b < 4; b++)
#pragma unroll
        for (int j = 0; j < 4; j++) {
            const __half* p = P +
                ((((size_t)(b * HH + bp * 4 + j)) << 10 | q) << 10) + ch * 8;
            uint4 u = *reinterpret_cast<const uint4*>(p);
            const __half2* h = reinterpret_cast<const __half2*>(&u);
            float f = sinv[row][b * 4 + j];
            float2 f0 = __half22float2(h[0]);
            float2 f1 = __half22float2(h[1]);
            float2 f2 = __half22float2(h[2]);
            float2 f3 = __half22float2(h[3]);
            a0 = fmaf(f0.x, f, a0); a1 = fmaf(f0.y, f, a1);
            a2 = fmaf(f1.x, f, a2); a3 = fmaf(f1.y, f, a3);
            a4 = fmaf(f2.x, f, a4); a5 = fmaf(f2.y, f, a5);
            a6 = fmaf(f3.x, f, a6); a7 = fmaf(f3.y, f, a7);
        }
    const float sc = 1.0f / 16.0f;
    float* dst = Aavg + (((size_t)(bp << 10 | q)) << 10) + ch * 8;
    *reinterpret_cast<float4*>(dst) =
        make_float4(a0 * sc, a1 * sc, a2 * sc, a3 * sc);
    *reinterpret_cast<float4*>(dst + 4) =
        make_float4(a4 * sc, a5 * sc, a6 * sc, a7 * sc);
}

// ---------------------------------------------------------------------------
#define PROJ_SMEM ((256 * PH + 128 * PH) * 2)

extern "C" void kernel_launch(void* const* d_in, const int* in_sizes, int n_in,
                              void* d_out, int out_size)
{
    const float* Q  = (const float*)d_in[0];
    const float* K  = (const float*)d_in[1];
    const float* Wq = (const float*)d_in[2];
    const float* bq = (const float*)d_in[3];
    const float* Wk = (const float*)d_in[4];
    const float* bk = (const float*)d_in[5];
    const float* Wv = (const float*)d_in[6];
    const float* bv = (const float*)d_in[7];

    float* O    = (float*)d_out;
    float* Aavg = O + (size_t)BB * NPQ * CDIM;

    static __half *pQh = nullptr, *pKh = nullptr, *pWh = nullptr;
    static __half *pq = nullptr, *pk = nullptr, *pv = nullptr, *pP = nullptr;
    static float* pR = nullptr;
    if (!pq) {
        cudaGetSymbolAddress((void**)&pQh, g_Qh);
        cudaGetSymbolAddress((void**)&pKh, g_Kh);
        cudaGetSymbolAddress((void**)&pWh, g_Wh);
        cudaGetSymbolAddress((void**)&pq, g_q);
        cudaGetSymbolAddress((void**)&pk, g_k);
        cudaGetSymbolAddress((void**)&pv, g_v);
        cudaGetSymbolAddress((void**)&pP, g_P);
        cudaGetSymbolAddress((void**)&pR, g_rowsum);
        cudaFuncSetAttribute(proj_gemm,
                             cudaFuncAttributeMaxDynamicSharedMemorySize, PROJ_SMEM);
        cudaFuncSetAttribute(fused_spv,
                             cudaFuncAttributeMaxDynamicSharedMemorySize, F_SMEM);
    }

    // 0) fp32 -> fp16 conversions
    const int NX4 = (BB * NPQ * CDIM) / 4;
    const int NW4 = (CDIM * CDIM) / 4;
    f2h_kernel<<<(NX4 + 255) / 256, 256>>>(Q, pQh, NX4);
    f2h_kernel<<<(NX4 + 255) / 256, 256>>>(K, pKh, NX4);
    f2h_kernel<<<(NW4 + 255) / 256, 256>>>(Wq, pWh, NW4);
    f2h_kernel<<<(NW4 + 255) / 256, 256>>>(Wk, pWh + (size_t)CDIM * CDIM, NW4);
    f2h_kernel<<<(NW4 + 255) / 256, 256>>>(Wv, pWh + 2 * (size_t)CDIM * CDIM, NW4);

    // 1) projections, batched
    dim3 gp(CDIM / 128, (BB * NPQ) / 256, 3);
    proj_gemm<<<gp, 256, PROJ_SMEM>>>(pQh, pKh, pWh, bq, bk, bv, pq, pk, pv);

    // 2) fused: P, rowsum, O in one pass (no memset, no atomics)
    dim3 gf(NPQ / 128, BB * HH);
    fused_spv<<<gf, 256, F_SMEM>>>(pq, pk, pv, pP, pR, O);

    // 3) A_avg
    avg_kernel<<<BB * (NPQ / 2), 256>>>(pP, pR, Aavg);
}

// round 13
// speedup vs baseline: 1.1336x; 1.0819x over previous
#include <cuda_runtime.h>
#include <cuda_fp16.h>
#include <cstdint>

#define BB   4
#define NPQ  1024
#define NRK  1024
#define CDIM 1024
#define HH   16
#define DH   64

// Scratch (static device arrays: allocation-guard safe)
__device__ __half g_Qh[(size_t)BB * NPQ * CDIM];
__device__ __half g_Kh[(size_t)BB * NRK * CDIM];
__device__ __half g_Wh[3 * (size_t)CDIM * CDIM];
__device__ __half g_q[(size_t)BB * NPQ * CDIM];
__device__ __half g_k[(size_t)BB * NRK * CDIM];
__device__ __half g_v[(size_t)BB * NRK * CDIM];
__device__ __half g_P[(size_t)BB * HH * NPQ * NRK];   // 128 MB
__device__ float  g_rowsum[(size_t)BB * HH * NPQ];

// ---------------------------------------------------------------------------
__device__ __forceinline__ void mma_f16(float c[4], const uint32_t a[4],
                                        const uint32_t b[2]) {
    asm volatile(
        "mma.sync.aligned.m16n8k16.row.col.f32.f16.f16.f32 "
        "{%0,%1,%2,%3}, {%4,%5,%6,%7}, {%8,%9}, {%0,%1,%2,%3};"
        : "+f"(c[0]), "+f"(c[1]), "+f"(c[2]), "+f"(c[3])
        : "r"(a[0]), "r"(a[1]), "r"(a[2]), "r"(a[3]), "r"(b[0]), "r"(b[1]));
}

#define LDSM_X4(r, addr) \
    asm volatile("ldmatrix.sync.aligned.m8n8.x4.shared.b16 {%0,%1,%2,%3}, [%4];" \
        : "=r"((r)[0]), "=r"((r)[1]), "=r"((r)[2]), "=r"((r)[3]) : "r"(addr))
#define LDSM_X2(r, addr) \
    asm volatile("ldmatrix.sync.aligned.m8n8.x2.shared.b16 {%0,%1}, [%2];" \
        : "=r"((r)[0]), "=r"((r)[1]) : "r"(addr))
#define LDSM_X2_T(r, addr) \
    asm volatile("ldmatrix.sync.aligned.m8n8.x2.trans.shared.b16 {%0,%1}, [%2];" \
        : "=r"((r)[0]), "=r"((r)[1]) : "r"(addr))

__device__ __forceinline__ uint32_t smem_u32(const void* p) {
    uint32_t a;
    asm("{ .reg .u64 t; cvta.to.shared.u64 t, %1; cvt.u32.u64 %0, t; }"
        : "=r"(a) : "l"(p));
    return a;
}

#define CP_ASYNC16(dst, src) \
    asm volatile("cp.async.cg.shared.global [%0], [%1], 16;" \
                 :: "r"(dst), "l"(src) : "memory")
#define CP_COMMIT() asm volatile("cp.async.commit_group;" ::: "memory")
#define CP_WAIT1()  asm volatile("cp.async.wait_group 1;" ::: "memory")
#define CP_WAIT0()  asm volatile("cp.async.wait_group 0;" ::: "memory")

#define SCH 72    // q/k smem halves stride
#define VSH 72    // v smem halves stride
#define PSH 136   // P smem halves stride (128 + 8 pad)
#define PH  40    // proj A/B halves stride (2x16 + 8 pad)

// fused kernel smem layout (halves)
#define FQ_OFF 0
#define FK_OFF (128 * SCH)
#define FV_OFF (FK_OFF + 2 * 128 * SCH)
#define FP_OFF (FV_OFF + 2 * 128 * VSH)
#define FR_OFF (FP_OFF + 128 * PSH)
#define F_SMEM ((FR_OFF + 256) * 2)         // 127488 B

// ---------------------------------------------------------------------------
// Merged fp32 -> fp16 conversion over 5 regions (one launch).
// Region table encoded by cumulative float4 counts.
// ---------------------------------------------------------------------------
__global__ void __launch_bounds__(256) f2h_all(
    const float* __restrict__ Q, const float* __restrict__ K,
    const float* __restrict__ Wq, const float* __restrict__ Wk,
    const float* __restrict__ Wv,
    __half* __restrict__ Qh, __half* __restrict__ Kh, __half* __restrict__ Wh)
{
    const int NX4 = (BB * NPQ * CDIM) / 4;    // 1048576
    const int NW4 = (CDIM * CDIM) / 4;        // 262144
    int i = blockIdx.x * 256 + threadIdx.x;

    const float* src;
    __half* dst;
    int off;
    if (i < NX4)                  { src = Q;  dst = Qh; off = i; }
    else if (i < 2 * NX4)         { src = K;  dst = Kh; off = i - NX4; }
    else if (i < 2 * NX4 + NW4)   { src = Wq; dst = Wh; off = i - 2 * NX4; }
    else if (i < 2 * NX4 + 2*NW4) { src = Wk; dst = Wh + (size_t)CDIM * CDIM;
                                    off = i - 2 * NX4 - NW4; }
    else if (i < 2 * NX4 + 3*NW4) { src = Wv; dst = Wh + 2 * (size_t)CDIM * CDIM;
                                    off = i - 2 * NX4 - 2 * NW4; }
    else return;

    float4 v = reinterpret_cast<const float4*>(src)[off];
    __half2* o = reinterpret_cast<__half2*>(dst) + 2 * (size_t)off;
    o[0] = __floats2half2_rn(v.x, v.y);
    o[1] = __floats2half2_rn(v.z, v.w);
}

// ---------------------------------------------------------------------------
// Projection GEMM (NT, fp16 HMMA), batched z in {0,1,2}.
// Block 128x128, 8 warps (4m x 2n), warp 32x64, k-stage 16, 2-stage cp.async,
// 2 CTAs/SM (scores-kernel resource shape).
// ---------------------------------------------------------------------------
__global__ void __launch_bounds__(256, 2) proj_gemm(
    const __half* __restrict__ Qh, const __half* __restrict__ Kh,
    const __half* __restrict__ Wh,
    const float* __restrict__ bq, const float* __restrict__ bk,
    const float* __restrict__ bv,
    __half* __restrict__ qo, __half* __restrict__ ko, __half* __restrict__ vo)
{
    extern __shared__ __half sh[];
    __half* Ah = sh;                 // [128][40]
    __half* Bh = sh + 128 * PH;      // [128][40]

    const int zz = blockIdx.z;
    const __half* Ag = (zz == 0) ? Qh : Kh;
    const __half* Bg = Wh + (size_t)zz * CDIM * CDIM;
    const float* bias = (zz == 0) ? bq : ((zz == 1) ? bk : bv);
    __half* Cg = (zz == 0) ? qo : ((zz == 1) ? ko : vo);

    const int tid = threadIdx.x;
    const int m0 = blockIdx.y << 7, n0 = blockIdx.x << 7;
    const int warp = tid >> 5, lane = tid & 31;
    const int g = lane >> 2, t = lane & 3;
    const int wm = (warp >> 1) << 5;   // 0,32,64,96
    const int wn = (warp & 1) << 6;    // 0,64

    const uint32_t sA = smem_u32(Ah);
    const uint32_t sB = smem_u32(Bh);

    auto load_stage = [&](int kt) {
        const int so = (kt & 1) << 4;
        const int k0 = kt << 4;
        {
            int r = tid >> 1, c = (tid & 1) << 3;
            CP_ASYNC16(sA + ((r * PH + so + c) << 1),
                       Ag + (size_t)(m0 + r) * CDIM + k0 + c);
            CP_ASYNC16(sB + ((r * PH + so + c) << 1),
                       Bg + (size_t)(n0 + r) * CDIM + k0 + c);
        }
        CP_COMMIT();
    };

    float acc[2][8][4];
#pragma unroll
    for (int i = 0; i < 2; i++)
#pragma unroll
        for (int j = 0; j < 8; j++)
#pragma unroll
            for (int l = 0; l < 4; l++) acc[i][j][l] = 0.f;

    const int KT = CDIM / 16;
    load_stage(0);

    const int arow = lane & 15, acol = (lane >> 4) << 3;
    const int brow = lane & 7,  bcol = ((lane >> 3) & 1) << 3;

    for (int kt = 0; kt < KT; kt++) {
        const bool pf = (kt + 1 < KT);
        if (pf) { load_stage(kt + 1); CP_WAIT1(); } else { CP_WAIT0(); }
        __syncthreads();

        const int so = (kt & 1) << 4;
        uint32_t a[2][4], b[8][2];
#pragma unroll
        for (int mt = 0; mt < 2; mt++)
            LDSM_X4(a[mt], sA + (((wm + (mt << 4) + arow) * PH) + so + acol) * 2);
#pragma unroll
        for (int nt = 0; nt < 8; nt++)
            LDSM_X2(b[nt], sB + (((wn + (nt << 3) + brow) * PH) + so + bcol) * 2);
#pragma unroll
        for (int mt = 0; mt < 2; mt++)
#pragma unroll
            for (int nt = 0; nt < 8; nt++)
                mma_f16(acc[mt][nt], a[mt], b[nt]);
        __syncthreads();
    }

#pragma unroll
    for (int mt = 0; mt < 2; mt++) {
        int m = m0 + wm + (mt << 4) + g;
#pragma unroll
        for (int nt = 0; nt < 8; nt++) {
            int n = n0 + wn + (nt << 3) + 2 * t;
            float b0v = bias[n], b1v = bias[n + 1];
            *reinterpret_cast<__half2*>(Cg + (size_t)m * CDIM + n) =
                __floats2half2_rn(acc[mt][nt][0] + b0v, acc[mt][nt][1] + b1v);
            *reinterpret_cast<__half2*>(Cg + (size_t)(m + 8) * CDIM + n) =
                __floats2half2_rn(acc[mt][nt][2] + b0v, acc[mt][nt][3] + b1v);
        }
    }
}

// ---------------------------------------------------------------------------
// Fused scores + PV per (z, q-tile).  [R12, rowsum from pre-rounded floats]
// ---------------------------------------------------------------------------
__global__ void __launch_bounds__(256, 1) fused_spv(
    const __half* __restrict__ qg, const __half* __restrict__ kg,
    const __half* __restrict__ vg,
    __half* __restrict__ Pg, float* __restrict__ rowsum,
    float* __restrict__ Og)
{
    extern __shared__ __half sh[];
    __half* qs = sh + FQ_OFF;
    __half* ps = sh + FP_OFF;
    float* rows_s = reinterpret_cast<float*>(sh + FR_OFF);

    const int tid = threadIdx.x;
    const int z = blockIdx.y;
    const long long zb = z >> 4, zh = z & 15;
    const __half* Aq = qg + zb * ((long long)NPQ * CDIM) + zh * DH;
    const __half* Ak = kg + zb * ((long long)NRK * CDIM) + zh * DH;
    const __half* Av = vg + zb * ((long long)NRK * CDIM) + zh * DH;
    __half* Pz = Pg + (long long)z * NPQ * NRK;
    float* Oz = Og + zb * ((long long)NPQ * CDIM) + zh * DH;

    const int m0 = blockIdx.x << 7;
    const int warp = tid >> 5, lane = tid & 31;
    const int g = lane >> 2, t = lane & 3;
    const int wm  = (warp >> 1) << 5;
    const int wnS = (warp & 1) << 6;
    const int wnO = (warp & 1) << 5;

    const uint32_t sq = smem_u32(qs);
    const uint32_t sk = smem_u32(sh + FK_OFF);
    const uint32_t sv = smem_u32(sh + FV_OFF);
    const uint32_t sp = smem_u32(ps);

    const int lrow = tid >> 1;
    const int lh = (tid & 1) << 5;

    auto load_kv = [&](int rc) {
        const int s = rc & 1;
        const int rbase = rc << 7;
        const __half* pk = Ak + (size_t)(rbase + lrow) * CDIM + lh;
        const __half* pv = Av + (size_t)(rbase + lrow) * CDIM + lh;
        const uint32_t dk = sk + ((s * 128 * SCH + lrow * SCH + lh) << 1);
        const uint32_t dv = sv + ((s * 128 * VSH + lrow * VSH + lh) << 1);
#pragma unroll
        for (int i = 0; i < 4; i++) {
            CP_ASYNC16(dk + (i << 4), pk + (i << 3));
            CP_ASYNC16(dv + (i << 4), pv + (i << 3));
        }
        CP_COMMIT();
    };

    {
        const __half* pa = Aq + (size_t)(m0 + lrow) * CDIM + lh;
        const uint32_t dq = sq + ((lrow * SCH + lh) << 1);
#pragma unroll
        for (int i = 0; i < 4; i++)
            CP_ASYNC16(dq + (i << 4), pa + (i << 3));
    }
    load_kv(0);

    if (tid < 128) rows_s[tid] = 0.f;

    float oacc[2][4][4];
#pragma unroll
    for (int i = 0; i < 2; i++)
#pragma unroll
        for (int j = 0; j < 4; j++)
#pragma unroll
            for (int l = 0; l < 4; l++) oacc[i][j][l] = 0.f;

    float rsum[2][2] = {{0.f, 0.f}, {0.f, 0.f}};

    const int arow = lane & 15, acol = (lane >> 4) << 3;
    const int brow = lane & 7,  bcol = ((lane >> 3) & 1) << 3;
    const int bkrow = lane & 15;
    const float alpha = 0.03125f;

    for (int rc = 0; rc < 8; rc++) {
        const int s = rc & 1;
        if (rc + 1 < 8) { load_kv(rc + 1); CP_WAIT1(); } else { CP_WAIT0(); }
        __syncthreads();

        float sacc[2][8][4];
#pragma unroll
        for (int i = 0; i < 2; i++)
#pragma unroll
            for (int j = 0; j < 8; j++)
#pragma unroll
                for (int l = 0; l < 4; l++) sacc[i][j][l] = 0.f;

#pragma unroll
        for (int kk = 0; kk < 64; kk += 16) {
            uint32_t a[2][4], b[8][2];
#pragma unroll
            for (int mt = 0; mt < 2; mt++)
                LDSM_X4(a[mt],
                        sq + (((wm + (mt << 4) + arow) * SCH) + kk + acol) * 2);
#pragma unroll
            for (int nt = 0; nt < 8; nt++)
                LDSM_X2(b[nt],
                        sk + ((s * 128 * SCH +
                               (wnS + (nt << 3) + brow) * SCH) + kk + bcol) * 2);
#pragma unroll
            for (int mt = 0; mt < 2; mt++)
#pragma unroll
                for (int nt = 0; nt < 8; nt++)
                    mma_f16(sacc[mt][nt], a[mt], b[nt]);
        }

        const int rbase = rc << 7;
#pragma unroll
        for (int mt = 0; mt < 2; mt++) {
            int mloc = wm + (mt << 4) + g;
#pragma unroll
            for (int nt = 0; nt < 8; nt++) {
                int n = wnS + (nt << 3) + 2 * t;
                float e0 = __expf(sacc[mt][nt][0] * alpha);
                float e1 = __expf(sacc[mt][nt][1] * alpha);
                float e2 = __expf(sacc[mt][nt][2] * alpha);
                float e3 = __expf(sacc[mt][nt][3] * alpha);
                rsum[mt][0] += e0 + e1;
                rsum[mt][1] += e2 + e3;
                __half2 p01 = __floats2half2_rn(e0, e1);
                __half2 p23 = __floats2half2_rn(e2, e3);
                *reinterpret_cast<__half2*>(
                    Pz + (size_t)(m0 + mloc) * NRK + rbase + n) = p01;
                *reinterpret_cast<__half2*>(
                    Pz + (size_t)(m0 + mloc + 8) * NRK + rbase + n) = p23;
                *reinterpret_cast<__half2*>(ps + mloc * PSH + n) = p01;
                *reinterpret_cast<__half2*>(ps + (mloc + 8) * PSH + n) = p23;
            }
        }
        __syncthreads();

#pragma unroll
        for (int kk = 0; kk < 128; kk += 16) {
            uint32_t a[2][4], b[4][2];
#pragma unroll
            for (int mt = 0; mt < 2; mt++)
                LDSM_X4(a[mt],
                        sp + (((wm + (mt << 4) + arow) * PSH) + kk + acol) * 2);
#pragma unroll
            for (int nt = 0; nt < 4; nt++)
                LDSM_X2_T(b[nt],
                          sv + ((s * 128 * VSH + (kk + bkrow) * VSH) +
                                wnO + (nt << 3)) * 2);
#pragma unroll
            for (int mt = 0; mt < 2; mt++)
#pragma unroll
                for (int nt = 0; nt < 4; nt++)
                    mma_f16(oacc[mt][nt], a[mt], b[nt]);
        }
        __syncthreads();
    }

#pragma unroll
    for (int mt = 0; mt < 2; mt++) {
        float r0 = rsum[mt][0], r1 = rsum[mt][1];
        r0 += __shfl_xor_sync(0xffffffffu, r0, 1);
        r0 += __shfl_xor_sync(0xffffffffu, r0, 2);
        r1 += __shfl_xor_sync(0xffffffffu, r1, 1);
        r1 += __shfl_xor_sync(0xffffffffu, r1, 2);
        if (t == 0) {
            atomicAdd(&rows_s[wm + (mt << 4) + g], r0);
            atomicAdd(&rows_s[wm + (mt << 4) + g + 8], r1);
        }
    }
    __syncthreads();
    if (tid < 128) {
        float sv_ = rows_s[tid];
        rowsum[(size_t)z * NPQ + m0 + tid] = sv_;
        rows_s[tid] = 1.0f / sv_;
    }
    __syncthreads();

#pragma unroll
    for (int mt = 0; mt < 2; mt++) {
        int mloc = wm + (mt << 4) + g;
        float i0 = rows_s[mloc];
        float i1 = rows_s[mloc + 8];
#pragma unroll
        for (int nt = 0; nt < 4; nt++) {
            int n = wnO + (nt << 3) + 2 * t;
            float2 o0, o1;
            o0.x = oacc[mt][nt][0] * i0; o0.y = oacc[mt][nt][1] * i0;
            o1.x = oacc[mt][nt][2] * i1; o1.y = oacc[mt][nt][3] * i1;
            *reinterpret_cast<float2*>(Oz + (size_t)(m0 + mloc) * CDIM + n) = o0;
            *reinterpret_cast<float2*>(Oz + (size_t)(m0 + mloc + 8) * CDIM + n) = o1;
        }
    }
}

// ---------------------------------------------------------------------------
// A_avg  [R11: 16B loads, bp reversed]
// ---------------------------------------------------------------------------
__global__ void __launch_bounds__(256) avg_kernel(
    const __half* __restrict__ P, const float* __restrict__ rowsum,
    float* __restrict__ Aavg)
{
    __shared__ float sinv[2][16];
    const int bp = 3 - (blockIdx.x >> 9);
    const int qp = blockIdx.x & 511;
    const int t = threadIdx.x;
    const int row = t >> 7;
    const int ch = t & 127;
    const int q = qp * 2 + row;

    if (t < 32) {
        int r2 = t >> 4, idx = t & 15;
        int b = idx >> 2, j = idx & 3;
        sinv[r2][idx] = 1.0f /
            rowsum[((size_t)(b * HH + bp * 4 + j)) * NPQ + qp * 2 + r2];
    }
    __syncthreads();

    float a0 = 0.f, a1 = 0.f, a2 = 0.f, a3 = 0.f;
    float a4 = 0.f, a5 = 0.f, a6 = 0.f, a7 = 0.f;
#pragma unroll
    for (int b = 0; b < 4; b++)
#pragma unroll
        for (int j = 0; j < 4; j++) {
            const __half* p = P +
                ((((size_t)(b * HH + bp * 4 + j)) << 10 | q) << 10) + ch * 8;
            uint4 u = *reinterpret_cast<const uint4*>(p);
            const __half2* h = reinterpret_cast<const __half2*>(&u);
            float f = sinv[row][b * 4 + j];
            float2 f0 = __half22float2(h[0]);
            float2 f1 = __half22float2(h[1]);
            float2 f2 = __half22float2(h[2]);
            float2 f3 = __half22float2(h[3]);
            a0 = fmaf(f0.x, f, a0); a1 = fmaf(f0.y, f, a1);
            a2 = fmaf(f1.x, f, a2); a3 = fmaf(f1.y, f, a3);
            a4 = fmaf(f2.x, f, a4); a5 = fmaf(f2.y, f, a5);
            a6 = fmaf(f3.x, f, a6); a7 = fmaf(f3.y, f, a7);
        }
    const float sc = 1.0f / 16.0f;
    float* dst = Aavg + (((size_t)(bp << 10 | q)) << 10) + ch * 8;
    *reinterpret_cast<float4*>(dst) =
        make_float4(a0 * sc, a1 * sc, a2 * sc, a3 * sc);
    *reinterpret_cast<float4*>(dst + 4) =
        make_float4(a4 * sc, a5 * sc, a6 * sc, a7 * sc);
}

// ---------------------------------------------------------------------------
#define PROJ_SMEM (2 * 128 * PH * 2)    // 20480 B

extern "C" void kernel_launch(void* const* d_in, const int* in_sizes, int n_in,
                              void* d_out, int out_size)
{
    const float* Q  = (const float*)d_in[0];
    const float* K  = (const float*)d_in[1];
    const float* Wq = (const float*)d_in[2];
    const float* bq = (const float*)d_in[3];
    const float* Wk = (const float*)d_in[4];
    const float* bk = (const float*)d_in[5];
    const float* Wv = (const float*)d_in[6];
    const float* bv = (const float*)d_in[7];

    float* O    = (float*)d_out;
    float* Aavg = O + (size_t)BB * NPQ * CDIM;

    static __half *pQh = nullptr, *pKh = nullptr, *pWh = nullptr;
    static __half *pq = nullptr, *pk = nullptr, *pv = nullptr, *pP = nullptr;
    static float* pR = nullptr;
    if (!pq) {
        cudaGetSymbolAddress((void**)&pQh, g_Qh);
        cudaGetSymbolAddress((void**)&pKh, g_Kh);
        cudaGetSymbolAddress((void**)&pWh, g_Wh);
        cudaGetSymbolAddress((void**)&pq, g_q);
        cudaGetSymbolAddress((void**)&pk, g_k);
        cudaGetSymbolAddress((void**)&pv, g_v);
        cudaGetSymbolAddress((void**)&pP, g_P);
        cudaGetSymbolAddress((void**)&pR, g_rowsum);
        cudaFuncSetAttribute(proj_gemm,
                             cudaFuncAttributeMaxDynamicSharedMemorySize, PROJ_SMEM);
        cudaFuncSetAttribute(fused_spv,
                             cudaFuncAttributeMaxDynamicSharedMemorySize, F_SMEM);
    }

    // 0) fp32 -> fp16 conversion, single launch over all 5 regions
    const int NX4 = (BB * NPQ * CDIM) / 4;
    const int NW4 = (CDIM * CDIM) / 4;
    const int TOT4 = 2 * NX4 + 3 * NW4;
    f2h_all<<<(TOT4 + 255) / 256, 256>>>(Q, K, Wq, Wk, Wv, pQh, pKh, pWh);

    // 1) projections, batched, 2 CTAs/SM
    dim3 gp(CDIM / 128, (BB * NPQ) / 128, 3);
    proj_gemm<<<gp, 256, PROJ_SMEM>>>(pQh, pKh, pWh, bq, bk, bv, pq, pk, pv);

    // 2) fused: P, rowsum, O in one pass
    dim3 gf(NPQ / 128, BB * HH);
    fused_spv<<<gf, 256, F_SMEM>>>(pq, pk, pv, pP, pR, O);

    // 3) A_avg
    avg_kernel<<<BB * (NPQ / 2), 256>>>(pP, pR, Aavg);
}

// round 16
// speedup vs baseline: 1.1585x; 1.0220x over previous
#include <cuda_runtime.h>
#include <cuda_fp16.h>
#include <cstdint>

#define BB   4
#define NPQ  1024
#define NRK  1024
#define CDIM 1024
#define HH   16
#define DH   64

// Scratch (static device arrays: allocation-guard safe)
__device__ __half g_Qh[(size_t)BB * NPQ * CDIM];
__device__ __half g_Kh[(size_t)BB * NRK * CDIM];
__device__ __half g_Wh[3 * (size_t)CDIM * CDIM];
__device__ __half g_q[(size_t)BB * NPQ * CDIM];
__device__ __half g_k[(size_t)BB * NRK * CDIM];
__device__ __half g_v[(size_t)BB * NRK * CDIM];
__device__ __half g_P[(size_t)BB * HH * NPQ * NRK];   // 128 MB
__device__ float  g_rowsum[(size_t)BB * HH * NPQ];

// ---------------------------------------------------------------------------
__device__ __forceinline__ uint32_t h2_bits(__half2 h) {
    return *reinterpret_cast<uint32_t*>(&h);
}

__device__ __forceinline__ void mma_f16(float c[4], const uint32_t a[4],
                                        const uint32_t b[2]) {
    asm volatile(
        "mma.sync.aligned.m16n8k16.row.col.f32.f16.f16.f32 "
        "{%0,%1,%2,%3}, {%4,%5,%6,%7}, {%8,%9}, {%0,%1,%2,%3};"
        : "+f"(c[0]), "+f"(c[1]), "+f"(c[2]), "+f"(c[3])
        : "r"(a[0]), "r"(a[1]), "r"(a[2]), "r"(a[3]), "r"(b[0]), "r"(b[1]));
}

#define LDSM_X4(r, addr) \
    asm volatile("ldmatrix.sync.aligned.m8n8.x4.shared.b16 {%0,%1,%2,%3}, [%4];" \
        : "=r"((r)[0]), "=r"((r)[1]), "=r"((r)[2]), "=r"((r)[3]) : "r"(addr))
#define LDSM_X2(r, addr) \
    asm volatile("ldmatrix.sync.aligned.m8n8.x2.shared.b16 {%0,%1}, [%2];" \
        : "=r"((r)[0]), "=r"((r)[1]) : "r"(addr))
#define LDSM_X2_T(r, addr) \
    asm volatile("ldmatrix.sync.aligned.m8n8.x2.trans.shared.b16 {%0,%1}, [%2];" \
        : "=r"((r)[0]), "=r"((r)[1]) : "r"(addr))

__device__ __forceinline__ uint32_t smem_u32(const void* p) {
    uint32_t a;
    asm("{ .reg .u64 t; cvta.to.shared.u64 t, %1; cvt.u32.u64 %0, t; }"
        : "=r"(a) : "l"(p));
    return a;
}

#define CP_ASYNC16(dst, src) \
    asm volatile("cp.async.cg.shared.global [%0], [%1], 16;" \
                 :: "r"(dst), "l"(src) : "memory")
#define CP_COMMIT() asm volatile("cp.async.commit_group;" ::: "memory")
#define CP_WAIT1()  asm volatile("cp.async.wait_group 1;" ::: "memory")
#define CP_WAIT0()  asm volatile("cp.async.wait_group 0;" ::: "memory")

#define SCH 72    // q/k smem halves stride
#define VSH 72    // v smem halves stride
#define PH  40    // proj A/B halves stride

// fused kernel smem layout (halves) — no P buffer (FA2 register fragments)
#define FQ_OFF 0
#define FK_OFF (128 * SCH)
#define FV_OFF (FK_OFF + 2 * 128 * SCH)
#define FR_OFF (FV_OFF + 2 * 128 * VSH)
#define F_SMEM ((FR_OFF + 256) * 2)         // 92672 B

// ---------------------------------------------------------------------------
// Merged fp32 -> fp16 conversion (one launch over 5 regions)
// ---------------------------------------------------------------------------
__global__ void __launch_bounds__(256) f2h_all(
    const float* __restrict__ Q, const float* __restrict__ K,
    const float* __restrict__ Wq, const float* __restrict__ Wk,
    const float* __restrict__ Wv,
    __half* __restrict__ Qh, __half* __restrict__ Kh, __half* __restrict__ Wh)
{
    const int NX4 = (BB * NPQ * CDIM) / 4;
    const int NW4 = (CDIM * CDIM) / 4;
    int i = blockIdx.x * 256 + threadIdx.x;

    const float* src;
    __half* dst;
    int off;
    if (i < NX4)                  { src = Q;  dst = Qh; off = i; }
    else if (i < 2 * NX4)         { src = K;  dst = Kh; off = i - NX4; }
    else if (i < 2 * NX4 + NW4)   { src = Wq; dst = Wh; off = i - 2 * NX4; }
    else if (i < 2 * NX4 + 2*NW4) { src = Wk; dst = Wh + (size_t)CDIM * CDIM;
                                    off = i - 2 * NX4 - NW4; }
    else if (i < 2 * NX4 + 3*NW4) { src = Wv; dst = Wh + 2 * (size_t)CDIM * CDIM;
                                    off = i - 2 * NX4 - 2 * NW4; }
    else return;

    float4 v = reinterpret_cast<const float4*>(src)[off];
    __half2* o = reinterpret_cast<__half2*>(dst) + 2 * (size_t)off;
    o[0] = __floats2half2_rn(v.x, v.y);
    o[1] = __floats2half2_rn(v.z, v.w);
}

// ---------------------------------------------------------------------------
// Projection GEMM (NT, fp16 HMMA), batched z in {0,1,2}. [R13]
// ---------------------------------------------------------------------------
__global__ void __launch_bounds__(256, 2) proj_gemm(
    const __half* __restrict__ Qh, const __half* __restrict__ Kh,
    const __half* __restrict__ Wh,
    const float* __restrict__ bq, const float* __restrict__ bk,
    const float* __restrict__ bv,
    __half* __restrict__ qo, __half* __restrict__ ko, __half* __restrict__ vo)
{
    extern __shared__ __half sh[];
    __half* Ah = sh;
    __half* Bh = sh + 128 * PH;

    const int zz = blockIdx.z;
    const __half* Ag = (zz == 0) ? Qh : Kh;
    const __half* Bg = Wh + (size_t)zz * CDIM * CDIM;
    const float* bias = (zz == 0) ? bq : ((zz == 1) ? bk : bv);
    __half* Cg = (zz == 0) ? qo : ((zz == 1) ? ko : vo);

    const int tid = threadIdx.x;
    const int m0 = blockIdx.y << 7, n0 = blockIdx.x << 7;
    const int warp = tid >> 5, lane = tid & 31;
    const int g = lane >> 2, t = lane & 3;
    const int wm = (warp >> 1) << 5;
    const int wn = (warp & 1) << 6;

    const uint32_t sA = smem_u32(Ah);
    const uint32_t sB = smem_u32(Bh);

    auto load_stage = [&](int kt) {
        const int so = (kt & 1) << 4;
        const int k0 = kt << 4;
        int r = tid >> 1, c = (tid & 1) << 3;
        CP_ASYNC16(sA + ((r * PH + so + c) << 1),
                   Ag + (size_t)(m0 + r) * CDIM + k0 + c);
        CP_ASYNC16(sB + ((r * PH + so + c) << 1),
                   Bg + (size_t)(n0 + r) * CDIM + k0 + c);
        CP_COMMIT();
    };

    float acc[2][8][4];
#pragma unroll
    for (int i = 0; i < 2; i++)
#pragma unroll
        for (int j = 0; j < 8; j++)
#pragma unroll
            for (int l = 0; l < 4; l++) acc[i][j][l] = 0.f;

    const int KT = CDIM / 16;
    load_stage(0);

    const int arow = lane & 15, acol = (lane >> 4) << 3;
    const int brow = lane & 7,  bcol = ((lane >> 3) & 1) << 3;

    for (int kt = 0; kt < KT; kt++) {
        const bool pf = (kt + 1 < KT);
        if (pf) { load_stage(kt + 1); CP_WAIT1(); } else { CP_WAIT0(); }
        __syncthreads();

        const int so = (kt & 1) << 4;
        uint32_t a[2][4], b[8][2];
#pragma unroll
        for (int mt = 0; mt < 2; mt++)
            LDSM_X4(a[mt], sA + (((wm + (mt << 4) + arow) * PH) + so + acol) * 2);
#pragma unroll
        for (int nt = 0; nt < 8; nt++)
            LDSM_X2(b[nt], sB + (((wn + (nt << 3) + brow) * PH) + so + bcol) * 2);
#pragma unroll
        for (int mt = 0; mt < 2; mt++)
#pragma unroll
            for (int nt = 0; nt < 8; nt++)
                mma_f16(acc[mt][nt], a[mt], b[nt]);
        __syncthreads();
    }

#pragma unroll
    for (int mt = 0; mt < 2; mt++) {
        int m = m0 + wm + (mt << 4) + g;
#pragma unroll
        for (int nt = 0; nt < 8; nt++) {
            int n = n0 + wn + (nt << 3) + 2 * t;
            float b0v = bias[n], b1v = bias[n + 1];
            *reinterpret_cast<__half2*>(Cg + (size_t)m * CDIM + n) =
                __floats2half2_rn(acc[mt][nt][0] + b0v, acc[mt][nt][1] + b1v);
            *reinterpret_cast<__half2*>(Cg + (size_t)(m + 8) * CDIM + n) =
                __floats2half2_rn(acc[mt][nt][2] + b0v, acc[mt][nt][3] + b1v);
        }
    }
}

// ---------------------------------------------------------------------------
// Fused scores + PV, FA2-style: P lives in registers as A fragments.
// Each warp: S tile 32x64 (wm, wnS); its S n-slice is its PV k-slice.
// Partial O (32x64) accumulated per warp; warp pairs reduced via smem at end.
// ---------------------------------------------------------------------------
__global__ void __launch_bounds__(256, 1) fused_spv(
    const __half* __restrict__ qg, const __half* __restrict__ kg,
    const __half* __restrict__ vg,
    __half* __restrict__ Pg, float* __restrict__ rowsum,
    float* __restrict__ Og)
{
    extern __shared__ __half sh[];
    __half* qs = sh + FQ_OFF;
    float* rows_s = reinterpret_cast<float*>(sh + FR_OFF);

    const int tid = threadIdx.x;
    const int z = blockIdx.y;
    const long long zb = z >> 4, zh = z & 15;
    const __half* Aq = qg + zb * ((long long)NPQ * CDIM) + zh * DH;
    const __half* Ak = kg + zb * ((long long)NRK * CDIM) + zh * DH;
    const __half* Av = vg + zb * ((long long)NRK * CDIM) + zh * DH;
    __half* Pz = Pg + (long long)z * NPQ * NRK;
    float* Oz = Og + zb * ((long long)NPQ * CDIM) + zh * DH;

    const int m0 = blockIdx.x << 7;
    const int warp = tid >> 5, lane = tid & 31;
    const int g = lane >> 2, t = lane & 3;
    const int wm  = (warp >> 1) << 5;   // 0,32,64,96
    const int wnS = (warp & 1) << 6;    // 0,64 : S cols = PV k-slice

    const uint32_t sq = smem_u32(qs);
    const uint32_t sk = smem_u32(sh + FK_OFF);
    const uint32_t sv = smem_u32(sh + FV_OFF);

    const int lrow = tid >> 1;
    const int lh = (tid & 1) << 5;

    auto load_kv = [&](int rc) {
        const int s = rc & 1;
        const int rbase = rc << 7;
        const __half* pk = Ak + (size_t)(rbase + lrow) * CDIM + lh;
        const __half* pv = Av + (size_t)(rbase + lrow) * CDIM + lh;
        const uint32_t dk = sk + ((s * 128 * SCH + lrow * SCH + lh) << 1);
        const uint32_t dv = sv + ((s * 128 * VSH + lrow * VSH + lh) << 1);
#pragma unroll
        for (int i = 0; i < 4; i++) {
            CP_ASYNC16(dk + (i << 4), pk + (i << 3));
            CP_ASYNC16(dv + (i << 4), pv + (i << 3));
        }
        CP_COMMIT();
    };

    {
        const __half* pa = Aq + (size_t)(m0 + lrow) * CDIM + lh;
        const uint32_t dq = sq + ((lrow * SCH + lh) << 1);
#pragma unroll
        for (int i = 0; i < 4; i++)
            CP_ASYNC16(dq + (i << 4), pa + (i << 3));
    }
    load_kv(0);

    if (tid < 128) rows_s[tid] = 0.f;

    float oacc[2][8][4];
#pragma unroll
    for (int i = 0; i < 2; i++)
#pragma unroll
        for (int j = 0; j < 8; j++)
#pragma unroll
            for (int l = 0; l < 4; l++) oacc[i][j][l] = 0.f;

    float rsum[2][2] = {{0.f, 0.f}, {0.f, 0.f}};

    const int arow = lane & 15, acol = (lane >> 4) << 3;
    const int brow = lane & 7,  bcol = ((lane >> 3) & 1) << 3;
    const int bkrow = lane & 15;
    const float alpha = 0.03125f;

    for (int rc = 0; rc < 8; rc++) {
        const int s = rc & 1;
        if (rc + 1 < 8) { load_kv(rc + 1); CP_WAIT1(); } else { CP_WAIT0(); }
        __syncthreads();

        // ---- S = q.k^T (warp: 32x64, K=64) ----
        float sacc[2][8][4];
#pragma unroll
        for (int i = 0; i < 2; i++)
#pragma unroll
            for (int j = 0; j < 8; j++)
#pragma unroll
                for (int l = 0; l < 4; l++) sacc[i][j][l] = 0.f;

#pragma unroll
        for (int kk = 0; kk < 64; kk += 16) {
            uint32_t a[2][4], b[8][2];
#pragma unroll
            for (int mt = 0; mt < 2; mt++)
                LDSM_X4(a[mt],
                        sq + (((wm + (mt << 4) + arow) * SCH) + kk + acol) * 2);
#pragma unroll
            for (int nt = 0; nt < 8; nt++)
                LDSM_X2(b[nt],
                        sk + ((s * 128 * SCH +
                               (wnS + (nt << 3) + brow) * SCH) + kk + bcol) * 2);
#pragma unroll
            for (int mt = 0; mt < 2; mt++)
#pragma unroll
                for (int nt = 0; nt < 8; nt++)
                    mma_f16(sacc[mt][nt], a[mt], b[nt]);
        }

        // ---- exp -> P gmem + register A-fragments (FA2) ----
        const int rbase = rc << 7;
        uint32_t pa[2][4][4];
#pragma unroll
        for (int mt = 0; mt < 2; mt++) {
            int mloc = wm + (mt << 4) + g;
#pragma unroll
            for (int j = 0; j < 4; j++) {
#pragma unroll
                for (int e = 0; e < 2; e++) {
                    int nt = 2 * j + e;
                    float e0 = __expf(sacc[mt][nt][0] * alpha);
                    float e1 = __expf(sacc[mt][nt][1] * alpha);
                    float e2 = __expf(sacc[mt][nt][2] * alpha);
                    float e3 = __expf(sacc[mt][nt][3] * alpha);
                    rsum[mt][0] += e0 + e1;
                    rsum[mt][1] += e2 + e3;
                    __half2 p01 = __floats2half2_rn(e0, e1);
                    __half2 p23 = __floats2half2_rn(e2, e3);
                    int n = wnS + (nt << 3) + 2 * t;
                    *reinterpret_cast<__half2*>(
                        Pz + (size_t)(m0 + mloc) * NRK + rbase + n) = p01;
                    *reinterpret_cast<__half2*>(
                        Pz + (size_t)(m0 + mloc + 8) * NRK + rbase + n) = p23;
                    pa[mt][j][2 * e]     = h2_bits(p01);
                    pa[mt][j][2 * e + 1] = h2_bits(p23);
                }
            }
        }

        // ---- O += P @ V over this warp's k-slice (wnS..wnS+63) ----
#pragma unroll
        for (int j = 0; j < 4; j++) {
            uint32_t b[8][2];
#pragma unroll
            for (int nt = 0; nt < 8; nt++)
                LDSM_X2_T(b[nt],
                          sv + ((s * 128 * VSH +
                                 (wnS + (j << 4) + bkrow) * VSH) + (nt << 3)) * 2);
#pragma unroll
            for (int mt = 0; mt < 2; mt++)
#pragma unroll
                for (int nt = 0; nt < 8; nt++)
                    mma_f16(oacc[mt][nt], pa[mt][j], b[nt]);
        }
        __syncthreads();   // k/v buffers free for next chunk
    }

    // ---- rowsum reduce + inv ----
#pragma unroll
    for (int mt = 0; mt < 2; mt++) {
        float r0 = rsum[mt][0], r1 = rsum[mt][1];
        r0 += __shfl_xor_sync(0xffffffffu, r0, 1);
        r0 += __shfl_xor_sync(0xffffffffu, r0, 2);
        r1 += __shfl_xor_sync(0xffffffffu, r1, 1);
        r1 += __shfl_xor_sync(0xffffffffu, r1, 2);
        if (t == 0) {
            atomicAdd(&rows_s[wm + (mt << 4) + g], r0);
            atomicAdd(&rows_s[wm + (mt << 4) + g + 8], r1);
        }
    }
    __syncthreads();
    if (tid < 128) {
        float sv_ = rows_s[tid];
        rowsum[(size_t)z * NPQ + m0 + tid] = sv_;
        rows_s[tid] = 1.0f / sv_;
    }
    __syncthreads();

    // ---- cross-warp-pair O reduction via smem (reuse k buffer region) ----
    float* scratch = reinterpret_cast<float*>(sh + FK_OFF);  // 4*32*64 floats
    const int wpair = warp >> 1;
    if (warp & 1) {
#pragma unroll
        for (int mt = 0; mt < 2; mt++) {
            int rl = (mt << 4) + g;
#pragma unroll
            for (int nt = 0; nt < 8; nt++) {
                int n = (nt << 3) + 2 * t;
                *reinterpret_cast<float2*>(
                    &scratch[(wpair * 32 + rl) * 64 + n]) =
                    make_float2(oacc[mt][nt][0], oacc[mt][nt][1]);
                *reinterpret_cast<float2*>(
                    &scratch[(wpair * 32 + rl + 8) * 64 + n]) =
                    make_float2(oacc[mt][nt][2], oacc[mt][nt][3]);
            }
        }
    }
    __syncthreads();
    if (!(warp & 1)) {
#pragma unroll
        for (int mt = 0; mt < 2; mt++) {
            int rl = (mt << 4) + g;
            int mloc = wm + rl;
            float i0 = rows_s[mloc];
            float i1 = rows_s[mloc + 8];
#pragma unroll
            for (int nt = 0; nt < 8; nt++) {
                int n = (nt << 3) + 2 * t;
                float2 s0 = *reinterpret_cast<const float2*>(
                    &scratch[(wpair * 32 + rl) * 64 + n]);
                float2 s1 = *reinterpret_cast<const float2*>(
                    &scratch[(wpair * 32 + rl + 8) * 64 + n]);
                float2 o0, o1;
                o0.x = (oacc[mt][nt][0] + s0.x) * i0;
                o0.y = (oacc[mt][nt][1] + s0.y) * i0;
                o1.x = (oacc[mt][nt][2] + s1.x) * i1;
                o1.y = (oacc[mt][nt][3] + s1.y) * i1;
                *reinterpret_cast<float2*>(
                    Oz + (size_t)(m0 + mloc) * CDIM + n) = o0;
                *reinterpret_cast<float2*>(
                    Oz + (size_t)(m0 + mloc + 8) * CDIM + n) = o1;
            }
        }
    }
}

// ---------------------------------------------------------------------------
// A_avg  [R11 shape]
// ---------------------------------------------------------------------------
__global__ void __launch_bounds__(256) avg_kernel(
    const __half* __restrict__ P, const float* __restrict__ rowsum,
    float* __restrict__ Aavg)
{
    __shared__ float sinv[2][16];
    const int bp = 3 - (blockIdx.x >> 9);
    const int qp = blockIdx.x & 511;
    const int t = threadIdx.x;
    const int row = t >> 7;
    const int ch = t & 127;
    const int q = qp * 2 + row;

    if (t < 32) {
        int r2 = t >> 4, idx = t & 15;
        int b = idx >> 2, j = idx & 3;
        sinv[r2][idx] = 1.0f /
            rowsum[((size_t)(b * HH + bp * 4 + j)) * NPQ + qp * 2 + r2];
    }
    __syncthreads();

    float a0 = 0.f, a1 = 0.f, a2 = 0.f, a3 = 0.f;
    float a4 = 0.f, a5 = 0.f, a6 = 0.f, a7 = 0.f;
#pragma unroll
    for (int b = 0; b < 4; b++)
#pragma unroll
        for (int j = 0; j < 4; j++) {
            const __half* p = P +
                ((((size_t)(b * HH + bp * 4 + j)) << 10 | q) << 10) + ch * 8;
            uint4 u = *reinterpret_cast<const uint4*>(p);
            const __half2* h = reinterpret_cast<const __half2*>(&u);
            float f = sinv[row][b * 4 + j];
            float2 f0 = __half22float2(h[0]);
            float2 f1 = __half22float2(h[1]);
            float2 f2 = __half22float2(h[2]);
            float2 f3 = __half22float2(h[3]);
            a0 = fmaf(f0.x, f, a0); a1 = fmaf(f0.y, f, a1);
            a2 = fmaf(f1.x, f, a2); a3 = fmaf(f1.y, f, a3);
            a4 = fmaf(f2.x, f, a4); a5 = fmaf(f2.y, f, a5);
            a6 = fmaf(f3.x, f, a6); a7 = fmaf(f3.y, f, a7);
        }
    const float sc = 1.0f / 16.0f;
    float* dst = Aavg + (((size_t)(bp << 10 | q)) << 10) + ch * 8;
    *reinterpret_cast<float4*>(dst) =
        make_float4(a0 * sc, a1 * sc, a2 * sc, a3 * sc);
    *reinterpret_cast<float4*>(dst + 4) =
        make_float4(a4 * sc, a5 * sc, a6 * sc, a7 * sc);
}

// ---------------------------------------------------------------------------
#define PROJ_SMEM (2 * 128 * PH * 2)    // 20480 B

extern "C" void kernel_launch(void* const* d_in, const int* in_sizes, int n_in,
                              void* d_out, int out_size)
{
    const float* Q  = (const float*)d_in[0];
    const float* K  = (const float*)d_in[1];
    const float* Wq = (const float*)d_in[2];
    const float* bq = (const float*)d_in[3];
    const float* Wk = (const float*)d_in[4];
    const float* bk = (const float*)d_in[5];
    const float* Wv = (const float*)d_in[6];
    const float* bv = (const float*)d_in[7];

    float* O    = (float*)d_out;
    float* Aavg = O + (size_t)BB * NPQ * CDIM;

    static __half *pQh = nullptr, *pKh = nullptr, *pWh = nullptr;
    static __half *pq = nullptr, *pk = nullptr, *pv = nullptr, *pP = nullptr;
    static float* pR = nullptr;
    if (!pq) {
        cudaGetSymbolAddress((void**)&pQh, g_Qh);
        cudaGetSymbolAddress((void**)&pKh, g_Kh);
        cudaGetSymbolAddress((void**)&pWh, g_Wh);
        cudaGetSymbolAddress((void**)&pq, g_q);
        cudaGetSymbolAddress((void**)&pk, g_k);
        cudaGetSymbolAddress((void**)&pv, g_v);
        cudaGetSymbolAddress((void**)&pP, g_P);
        cudaGetSymbolAddress((void**)&pR, g_rowsum);
        cudaFuncSetAttribute(proj_gemm,
                             cudaFuncAttributeMaxDynamicSharedMemorySize, PROJ_SMEM);
        cudaFuncSetAttribute(fused_spv,
                             cudaFuncAttributeMaxDynamicSharedMemorySize, F_SMEM);
    }

    // 0) fp32 -> fp16 conversion
    const int NX4 = (BB * NPQ * CDIM) / 4;
    const int NW4 = (CDIM * CDIM) / 4;
    const int TOT4 = 2 * NX4 + 3 * NW4;
    f2h_all<<<(TOT4 + 255) / 256, 256>>>(Q, K, Wq, Wk, Wv, pQh, pKh, pWh);

    // 1) projections
    dim3 gp(CDIM / 128, (BB * NPQ) / 128, 3);
    proj_gemm<<<gp, 256, PROJ_SMEM>>>(pQh, pKh, pWh, bq, bk, bv, pq, pk, pv);

    // 2) fused: P, rowsum, O (FA2 register-fragment P)
    dim3 gf(NPQ / 128, BB * HH);
    fused_spv<<<gf, 256, F_SMEM>>>(pq, pk, pv, pP, pR, O);

    // 3) A_avg
    avg_kernel<<<BB * (NPQ / 2), 256>>>(pP, pR, Aavg);
}